// round 8
// baseline (speedup 1.0000x reference)
#include <cuda_runtime.h>
#include <cuda_fp16.h>
#include <cstdint>

#define BDIM   64
#define IOD    8192
#define OTILE  64
#define KC     64
#define KSPLIT 2
#define KHALF  (IOD / KSPLIT)      // 4096
#define NITER  (KHALF / KC)        // 64
#define STAGE_BYTES (2 * 8192)     // W(8KB fp16 ternary) + X(8KB fp16)

// scratch (no cudaMalloc allowed)
__device__ float g_part[KSPLIT][BDIM * IOD];   // split-K partials (alpha applied, no bias)

// 128B-row XOR swizzle (Swizzle<3,4,3>) — conflict-free STS + ldmatrix
__device__ __forceinline__ uint32_t swz(uint32_t off) {
    return off ^ ((off >> 3) & 0x70);
}

__device__ __forceinline__ void ldm_x4(uint32_t& r0, uint32_t& r1,
                                       uint32_t& r2, uint32_t& r3, uint32_t addr) {
    asm volatile("ldmatrix.sync.aligned.m8n8.x4.shared.b16 {%0,%1,%2,%3}, [%4];"
                 : "=r"(r0), "=r"(r1), "=r"(r2), "=r"(r3) : "r"(addr));
}

__device__ __forceinline__ void mma_f16(float* c,
                                        uint32_t a0, uint32_t a1, uint32_t a2, uint32_t a3,
                                        uint32_t b0, uint32_t b1) {
    asm volatile("mma.sync.aligned.m16n8k16.row.col.f32.f16.f16.f32 "
                 "{%0,%1,%2,%3}, {%4,%5,%6,%7}, {%8,%9}, {%0,%1,%2,%3};"
                 : "+f"(c[0]), "+f"(c[1]), "+f"(c[2]), "+f"(c[3])
                 : "r"(a0), "r"(a1), "r"(a2), "r"(a3), "r"(b0), "r"(b1));
}

// ternary quantize one fp32 -> fp16 {-1, 0, +1} bit pattern (alpha applied in epilogue)
__device__ __forceinline__ uint32_t quant1(float f, float thr) {
    uint32_t u = __float_as_uint(f);
    return (fabsf(f) > thr) ? (0x3C00u | ((u >> 16) & 0x8000u)) : 0u;
}

__device__ __forceinline__ uint32_t packh2(float a, float b) {
    __half2 h = __floats2half2_rn(a, b);
    return *reinterpret_cast<uint32_t*>(&h);
}

__device__ __forceinline__ void load_w(const float* __restrict__ wgt,
                                       int n0, int wr, int wc, int kbase,
                                       uint4 wreg[4]) {
#pragma unroll
    for (int p = 0; p < 4; ++p)
        wreg[p] = *reinterpret_cast<const uint4*>(
            wgt + (size_t)(n0 + wr + 16 * p) * IOD + kbase + wc * 4);
}

// load 16 fp32 x elems and pack to fp16 (two 8-elem chunks, 32 k apart)
__device__ __forceinline__ void load_x(const float* __restrict__ x,
                                       int xm, int xc, int kbase, uint4 xh[2]) {
#pragma unroll
    for (int c2 = 0; c2 < 2; ++c2) {
        const float* p = x + (size_t)xm * IOD + kbase + (xc + 4 * c2) * 8;
        float4 a = *reinterpret_cast<const float4*>(p);
        float4 b = *reinterpret_cast<const float4*>(p + 4);
        xh[c2].x = packh2(a.x, a.y);
        xh[c2].y = packh2(a.z, a.w);
        xh[c2].z = packh2(b.x, b.y);
        xh[c2].w = packh2(b.z, b.w);
    }
}

__device__ __forceinline__ void store_tile(unsigned char* smem, int stage,
                                           int wr, int wc, int xm, int xc,
                                           const float thr[4],
                                           const uint4 wreg[4], const uint4 xh[2]) {
    unsigned char* base = smem + stage * STAGE_BYTES;
#pragma unroll
    for (int p = 0; p < 4; ++p) {
        uint32_t q0 = quant1(__uint_as_float(wreg[p].x), thr[p]);
        uint32_t q1 = quant1(__uint_as_float(wreg[p].y), thr[p]);
        uint32_t q2 = quant1(__uint_as_float(wreg[p].z), thr[p]);
        uint32_t q3 = quant1(__uint_as_float(wreg[p].w), thr[p]);
        uint2 v;
        v.x = q0 | (q1 << 16);
        v.y = q2 | (q3 << 16);
        *reinterpret_cast<uint2*>(base + swz((wr + 16 * p) * 128 + wc * 8)) = v;
    }
#pragma unroll
    for (int c2 = 0; c2 < 2; ++c2) {
        int c = xc + 4 * c2;
        uint32_t off = swz(xm * 128 + c * 16);
        *reinterpret_cast<uint4*>(base + 8192 + off) = xh[c2];
    }
}

__device__ __forceinline__ void mma_stage(uint32_t smem_base, int stage,
                                          int m_base, int n_base, int lrow, int lk16,
                                          float acc[2][2][4]) {
    uint32_t wb = smem_base + stage * STAGE_BYTES;
#pragma unroll
    for (int ks = 0; ks < 4; ++ks) {
        int kb = ks * 32 + lk16;
        uint32_t b0, b1, b2, b3;
        ldm_x4(b0, b1, b2, b3, wb + swz((n_base + lrow) * 128 + kb));
        uint32_t ah[2][4];
#pragma unroll
        for (int mt = 0; mt < 2; ++mt) {
            uint32_t roff = swz((m_base + mt * 16 + lrow) * 128 + kb);
            ldm_x4(ah[mt][0], ah[mt][1], ah[mt][2], ah[mt][3], wb + 8192 + roff);
        }
#pragma unroll
        for (int mt = 0; mt < 2; ++mt) {
            mma_f16(acc[mt][0], ah[mt][0], ah[mt][1], ah[mt][2], ah[mt][3], b0, b2);
            mma_f16(acc[mt][1], ah[mt][0], ah[mt][1], ah[mt][2], ah[mt][3], b1, b3);
        }
    }
}

__global__ __launch_bounds__(256, 2) void qlin(
    const float* __restrict__ x,
    const float* __restrict__ wgt,
    const float* __restrict__ alpha)
{
    __shared__ __align__(1024) unsigned char smem[2 * STAGE_BYTES];  // 32KB

    const int otile  = blockIdx.x & 127;
    const int khalf  = blockIdx.x >> 7;
    const int n0     = otile * OTILE;
    const int k0     = khalf * KHALF;

    const int tid  = threadIdx.x;
    const int lane = tid & 31;
    const int warp = tid >> 5;
    const int m_base = (warp >> 2) * 32;   // 2 warp rows (M)
    const int n_base = (warp & 3) * 16;    // 4 warp cols (N)

    const uint32_t smem_base = (uint32_t)__cvta_generic_to_shared(smem);

    // weight loader mapping: 16 threads per O-row, 16 rows per pass, 4 passes
    const int wr = tid >> 4;
    const int wc = tid & 15;
    float thr[4];
#pragma unroll
    for (int p = 0; p < 4; ++p)
        thr[p] = 0.5f * (alpha[n0 + wr + 16 * p] + 1e-8f);

    // x loader mapping: 4 threads per batch row
    const int xm = tid >> 2;
    const int xc = tid & 3;

    float acc[2][2][4];
#pragma unroll
    for (int i = 0; i < 2; ++i)
#pragma unroll
        for (int j = 0; j < 2; ++j)
#pragma unroll
            for (int k = 0; k < 4; ++k) acc[i][j][k] = 0.0f;

    const int lrow = lane & 15;
    const int lk16 = (lane >> 4) * 16;

    uint4 wbuf[2][4], xh[2];

    // prologue: stage 0 filled; W(1) prefetched
    load_w(wgt, n0, wr, wc, k0, wbuf[0]);
    load_x(x, xm, xc, k0, xh);
    store_tile(smem, 0, wr, wc, xm, xc, thr, wbuf[0], xh);
    load_w(wgt, n0, wr, wc, k0 + KC, wbuf[1]);
    __syncthreads();

    for (int it = 0; it < NITER; ++it) {
        const int cur = it & 1;
        // W prefetched 2 tiles ahead (reuses the buffer whose tile is already stored)
        if (it + 2 < NITER)
            load_w(wgt, n0, wr, wc, k0 + (it + 2) * KC, wbuf[cur]);
        if (it + 1 < NITER)
            load_x(x, xm, xc, k0 + (it + 1) * KC, xh);

        mma_stage(smem_base, cur, m_base, n_base, lrow, lk16, acc);

        if (it + 1 < NITER)
            store_tile(smem, cur ^ 1, wr, wc, xm, xc, thr, wbuf[cur ^ 1], xh);
        __syncthreads();
    }

    // epilogue: partial[b,o] = alpha[o] * acc   (bias added in reduce)
    float* part = g_part[khalf];
#pragma unroll
    for (int mt = 0; mt < 2; ++mt) {
#pragma unroll
        for (int nt = 0; nt < 2; ++nt) {
            int brow = m_base + mt * 16 + (lane >> 2);
            int o0   = n0 + n_base + nt * 8 + (lane & 3) * 2;
            float2 a2 = *reinterpret_cast<const float2*>(alpha + o0);
            float2 v0, v1;
            v0.x = acc[mt][nt][0] * a2.x;
            v0.y = acc[mt][nt][1] * a2.y;
            v1.x = acc[mt][nt][2] * a2.x;
            v1.y = acc[mt][nt][3] * a2.y;
            *reinterpret_cast<float2*>(part + (size_t)brow * IOD + o0)       = v0;
            *reinterpret_cast<float2*>(part + (size_t)(brow + 8) * IOD + o0) = v1;
        }
    }
}

__global__ void reduce_k(const float* __restrict__ bias, float* __restrict__ out) {
    int i = blockIdx.x * blockDim.x + threadIdx.x;     // float4 index
    if (i < (BDIM * IOD) / 4) {
        float4 p0 = reinterpret_cast<const float4*>(g_part[0])[i];
        float4 p1 = reinterpret_cast<const float4*>(g_part[1])[i];
        int o = (i * 4) & (IOD - 1);
        float4 b = *reinterpret_cast<const float4*>(bias + o);
        float4 r;
        r.x = p0.x + p1.x + b.x;
        r.y = p0.y + p1.y + b.y;
        r.z = p0.z + p1.z + b.z;
        r.w = p0.w + p1.w + b.w;
        reinterpret_cast<float4*>(out)[i] = r;
    }
}

extern "C" void kernel_launch(void* const* d_in, const int* in_sizes, int n_in,
                              void* d_out, int out_size) {
    const float* x     = (const float*)d_in[0];
    const float* wgt   = (const float*)d_in[1];
    const float* alpha = (const float*)d_in[2];
    const float* bias  = (const float*)d_in[3];
    float* out = (float*)d_out;

    qlin<<<(IOD / OTILE) * KSPLIT, 256>>>(x, wgt, alpha);
    reduce_k<<<((BDIM * IOD / 4) + 255) / 256, 256>>>(bias, out);
}

// round 9
// speedup vs baseline: 1.4425x; 1.4425x over previous
#include <cuda_runtime.h>
#include <cuda_fp16.h>
#include <cstdint>

#define BDIM   64
#define IOD    8192
#define OTILE  64
#define KC     64
#define KSPLIT 2
#define KHALF  (IOD / KSPLIT)      // 4096
#define NITER  (KHALF / KC)        // 64
#define STAGE_BYTES (2 * 8192)     // W(8KB fp16 ternary) + X(8KB fp16)

// scratch (no cudaMalloc allowed)
__device__ __half g_xh[BDIM * IOD];            // x in fp16 (single pass)
__device__ float g_part[KSPLIT][BDIM * IOD];   // split-K partials (alpha applied, no bias)
__device__ unsigned int g_cnt[IOD / OTILE];    // per-otile completion counters

__global__ void prep_x(const float* __restrict__ x) {
    int i = blockIdx.x * blockDim.x + threadIdx.x;   // float4 index
    if (i < (BDIM * IOD) / 4) {
        float4 v = reinterpret_cast<const float4*>(x)[i];
        __half2 h01, h23;
        h01.x = __float2half_rn(v.x);
        h01.y = __float2half_rn(v.y);
        h23.x = __float2half_rn(v.z);
        h23.y = __float2half_rn(v.w);
        reinterpret_cast<__half2*>(g_xh)[i * 2]     = h01;
        reinterpret_cast<__half2*>(g_xh)[i * 2 + 1] = h23;
    }
}

// 128B-row XOR swizzle (Swizzle<3,4,3>) — conflict-free STS + ldmatrix
__device__ __forceinline__ uint32_t swz(uint32_t off) {
    return off ^ ((off >> 3) & 0x70);
}

__device__ __forceinline__ void ldm_x4(uint32_t& r0, uint32_t& r1,
                                       uint32_t& r2, uint32_t& r3, uint32_t addr) {
    asm volatile("ldmatrix.sync.aligned.m8n8.x4.shared.b16 {%0,%1,%2,%3}, [%4];"
                 : "=r"(r0), "=r"(r1), "=r"(r2), "=r"(r3) : "r"(addr));
}

__device__ __forceinline__ void mma_f16(float* c,
                                        uint32_t a0, uint32_t a1, uint32_t a2, uint32_t a3,
                                        uint32_t b0, uint32_t b1) {
    asm volatile("mma.sync.aligned.m16n8k16.row.col.f32.f16.f16.f32 "
                 "{%0,%1,%2,%3}, {%4,%5,%6,%7}, {%8,%9}, {%0,%1,%2,%3};"
                 : "+f"(c[0]), "+f"(c[1]), "+f"(c[2]), "+f"(c[3])
                 : "r"(a0), "r"(a1), "r"(a2), "r"(a3), "r"(b0), "r"(b1));
}

// ternary quantize one fp32 -> fp16 {-1, 0, +1} bit pattern (alpha applied in epilogue)
__device__ __forceinline__ uint32_t quant1(float f, float thr) {
    uint32_t u = __float_as_uint(f);
    return (fabsf(f) > thr) ? (0x3C00u | ((u >> 16) & 0x8000u)) : 0u;
}

__device__ __forceinline__ void load_tile(const float* __restrict__ wgt,
                                          int n0, int wr, int wc, int xm, int xc, int kbase,
                                          uint4 wreg[4], uint4 xh[2]) {
#pragma unroll
    for (int p = 0; p < 4; ++p)
        wreg[p] = *reinterpret_cast<const uint4*>(
            wgt + (size_t)(n0 + wr + 16 * p) * IOD + kbase + wc * 4);
#pragma unroll
    for (int c2 = 0; c2 < 2; ++c2) {
        int c = xc + 4 * c2;
        xh[c2] = *reinterpret_cast<const uint4*>(&g_xh[(size_t)xm * IOD + kbase + c * 8]);
    }
}

__device__ __forceinline__ void store_tile(unsigned char* smem, int stage,
                                           int wr, int wc, int xm, int xc,
                                           const float thr[4],
                                           const uint4 wreg[4], const uint4 xh[2]) {
    unsigned char* base = smem + stage * STAGE_BYTES;
#pragma unroll
    for (int p = 0; p < 4; ++p) {
        uint32_t q0 = quant1(__uint_as_float(wreg[p].x), thr[p]);
        uint32_t q1 = quant1(__uint_as_float(wreg[p].y), thr[p]);
        uint32_t q2 = quant1(__uint_as_float(wreg[p].z), thr[p]);
        uint32_t q3 = quant1(__uint_as_float(wreg[p].w), thr[p]);
        uint2 v;
        v.x = q0 | (q1 << 16);
        v.y = q2 | (q3 << 16);
        *reinterpret_cast<uint2*>(base + swz((wr + 16 * p) * 128 + wc * 8)) = v;
    }
#pragma unroll
    for (int c2 = 0; c2 < 2; ++c2) {
        int c = xc + 4 * c2;
        uint32_t off = swz(xm * 128 + c * 16);
        *reinterpret_cast<uint4*>(base + 8192 + off) = xh[c2];
    }
}

__device__ __forceinline__ void mma_stage(uint32_t smem_base, int stage,
                                          int m_base, int n_base, int lrow, int lk16,
                                          float acc[2][2][4]) {
    uint32_t wb = smem_base + stage * STAGE_BYTES;
#pragma unroll
    for (int ks = 0; ks < 4; ++ks) {
        int kb = ks * 32 + lk16;
        uint32_t b0, b1, b2, b3;
        ldm_x4(b0, b1, b2, b3, wb + swz((n_base + lrow) * 128 + kb));
        uint32_t ah[2][4];
#pragma unroll
        for (int mt = 0; mt < 2; ++mt) {
            uint32_t roff = swz((m_base + mt * 16 + lrow) * 128 + kb);
            ldm_x4(ah[mt][0], ah[mt][1], ah[mt][2], ah[mt][3], wb + 8192 + roff);
        }
#pragma unroll
        for (int mt = 0; mt < 2; ++mt) {
            mma_f16(acc[mt][0], ah[mt][0], ah[mt][1], ah[mt][2], ah[mt][3], b0, b2);
            mma_f16(acc[mt][1], ah[mt][0], ah[mt][1], ah[mt][2], ah[mt][3], b1, b3);
        }
    }
}

__global__ __launch_bounds__(256, 2) void qlin(
    const float* __restrict__ wgt,
    const float* __restrict__ alpha,
    const float* __restrict__ bias,
    float* __restrict__ out)
{
    __shared__ __align__(1024) unsigned char smem[2 * STAGE_BYTES];  // 32KB
    __shared__ unsigned int s_last;

    const int otile  = blockIdx.x & 127;
    const int khalf  = blockIdx.x >> 7;
    const int n0     = otile * OTILE;
    const int k0     = khalf * KHALF;

    const int tid  = threadIdx.x;
    const int lane = tid & 31;
    const int warp = tid >> 5;
    const int m_base = (warp >> 2) * 32;   // 2 warp rows (M)
    const int n_base = (warp & 3) * 16;    // 4 warp cols (N)

    const uint32_t smem_base = (uint32_t)__cvta_generic_to_shared(smem);

    // weight loader mapping: 16 threads per O-row, 16 rows per pass, 4 passes
    const int wr = tid >> 4;
    const int wc = tid & 15;
    float thr[4];
#pragma unroll
    for (int p = 0; p < 4; ++p)
        thr[p] = 0.5f * (alpha[n0 + wr + 16 * p] + 1e-8f);

    // x loader mapping: 4 threads per batch row
    const int xm = tid >> 2;
    const int xc = tid & 3;

    float acc[2][2][4];
#pragma unroll
    for (int i = 0; i < 2; ++i)
#pragma unroll
        for (int j = 0; j < 2; ++j)
#pragma unroll
            for (int k = 0; k < 4; ++k) acc[i][j][k] = 0.0f;

    const int lrow = lane & 15;
    const int lk16 = (lane >> 4) * 16;

    uint4 wreg[4], xh[2];

    // prologue: fill stage 0
    load_tile(wgt, n0, wr, wc, xm, xc, k0, wreg, xh);
    store_tile(smem, 0, wr, wc, xm, xc, thr, wreg, xh);
    __syncthreads();

    for (int it = 0; it < NITER; ++it) {
        const int cur = it & 1;
        if (it + 1 < NITER)
            load_tile(wgt, n0, wr, wc, xm, xc, k0 + (it + 1) * KC, wreg, xh);

        mma_stage(smem_base, cur, m_base, n_base, lrow, lk16, acc);

        if (it + 1 < NITER)
            store_tile(smem, cur ^ 1, wr, wc, xm, xc, thr, wreg, xh);
        __syncthreads();
    }

    // scale by alpha in regs, write partial, then last CTA of the pair reduces
    float* part = g_part[khalf];
#pragma unroll
    for (int mt = 0; mt < 2; ++mt) {
#pragma unroll
        for (int nt = 0; nt < 2; ++nt) {
            int brow = m_base + mt * 16 + (lane >> 2);
            int o0   = n0 + n_base + nt * 8 + (lane & 3) * 2;
            float2 a2 = *reinterpret_cast<const float2*>(alpha + o0);
            acc[mt][nt][0] *= a2.x;
            acc[mt][nt][1] *= a2.y;
            acc[mt][nt][2] *= a2.x;
            acc[mt][nt][3] *= a2.y;
            float2 v0 = make_float2(acc[mt][nt][0], acc[mt][nt][1]);
            float2 v1 = make_float2(acc[mt][nt][2], acc[mt][nt][3]);
            *reinterpret_cast<float2*>(part + (size_t)brow * IOD + o0)       = v0;
            *reinterpret_cast<float2*>(part + (size_t)(brow + 8) * IOD + o0) = v1;
        }
    }

    __threadfence();
    __syncthreads();
    if (tid == 0) {
        unsigned int old = atomicAdd(&g_cnt[otile], 1u);
        s_last = (((old + 1) % KSPLIT) == 0) ? 1u : 0u;
    }
    __syncthreads();

    if (s_last) {
        // this CTA finished second: its alpha*acc is in regs; add the other half + bias
        const float* other = g_part[khalf ^ 1];
#pragma unroll
        for (int mt = 0; mt < 2; ++mt) {
#pragma unroll
            for (int nt = 0; nt < 2; ++nt) {
                int brow = m_base + mt * 16 + (lane >> 2);
                int o0   = n0 + n_base + nt * 8 + (lane & 3) * 2;
                float2 bi = *reinterpret_cast<const float2*>(bias + o0);
                float2 p0 = *reinterpret_cast<const float2*>(other + (size_t)brow * IOD + o0);
                float2 p1 = *reinterpret_cast<const float2*>(other + (size_t)(brow + 8) * IOD + o0);
                float2 v0, v1;
                v0.x = acc[mt][nt][0] + p0.x + bi.x;
                v0.y = acc[mt][nt][1] + p0.y + bi.y;
                v1.x = acc[mt][nt][2] + p1.x + bi.x;
                v1.y = acc[mt][nt][3] + p1.y + bi.y;
                *reinterpret_cast<float2*>(out + (size_t)brow * IOD + o0)       = v0;
                *reinterpret_cast<float2*>(out + (size_t)(brow + 8) * IOD + o0) = v1;
            }
        }
    }
}

extern "C" void kernel_launch(void* const* d_in, const int* in_sizes, int n_in,
                              void* d_out, int out_size) {
    const float* x     = (const float*)d_in[0];
    const float* wgt   = (const float*)d_in[1];
    const float* alpha = (const float*)d_in[2];
    const float* bias  = (const float*)d_in[3];
    float* out = (float*)d_out;

    prep_x<<<((BDIM * IOD / 4) + 255) / 256, 256>>>(x);
    qlin<<<(IOD / OTILE) * KSPLIT, 256>>>(wgt, alpha, bias, out);
}